// round 7
// baseline (speedup 1.0000x reference)
#include <cuda_runtime.h>
#include <cuda_bf16.h>
#include <math.h>
#include <stdint.h>

#define BB   2
#define SS   2048
#define DD   2048
#define HH   16
#define KVH  8
#define GG   2
#define HD   128
#define SCALE 0.08838834764831845f

typedef __nv_bfloat16 bf16;
typedef __nv_bfloat162 bf162;

// ---------------- persistent scratch ----------------
__device__ float g_q[8388608];                     // (B,S,H,HD) fp32 pre-norm
__device__ float g_k[4194304];                     // (B,S,KV,HD)
__device__ bf16 xs_h[8388608],  xs_l[8388608];
__device__ bf16 wqs_h[4194304], wqs_l[4194304];
__device__ bf16 wks_h[2097152], wks_l[2097152];
__device__ bf16 wvs_h[2097152], wvs_l[2097152];
__device__ bf16 wos_h[4194304], wos_l[4194304];
__device__ bf16 qs_h[8388608],  qs_l[8388608];
__device__ bf16 ks_h[4194304],  ks_l[4194304];
__device__ bf16 vs_h[4194304],  vs_l[4194304];
__device__ bf16 os_h[8388608],  os_l[8388608];

// ---------------- PTX helpers ----------------
__device__ __forceinline__ uint32_t smaddr(const void* p) {
    return (uint32_t)__cvta_generic_to_shared(p);
}
__device__ __forceinline__ void ldsm_x4(uint32_t* r, uint32_t addr) {
    asm volatile("ldmatrix.sync.aligned.m8n8.x4.shared.b16 {%0,%1,%2,%3}, [%4];"
        : "=r"(r[0]), "=r"(r[1]), "=r"(r[2]), "=r"(r[3]) : "r"(addr));
}
__device__ __forceinline__ void ldsm_x2t(uint32_t* r, uint32_t addr) {
    asm volatile("ldmatrix.sync.aligned.m8n8.x2.trans.shared.b16 {%0,%1}, [%2];"
        : "=r"(r[0]), "=r"(r[1]) : "r"(addr));
}
__device__ __forceinline__ void mma_bf16(float* c, const uint32_t* a, const uint32_t* b) {
    asm volatile(
        "mma.sync.aligned.m16n8k16.row.col.f32.bf16.bf16.f32 "
        "{%0,%1,%2,%3}, {%4,%5,%6,%7}, {%8,%9}, {%0,%1,%2,%3};"
        : "+f"(c[0]), "+f"(c[1]), "+f"(c[2]), "+f"(c[3])
        : "r"(a[0]), "r"(a[1]), "r"(a[2]), "r"(a[3]), "r"(b[0]), "r"(b[1]));
}
__device__ __forceinline__ void split2(float x, float y, bf162& h, bf162& l) {
    h = __floats2bfloat162_rn(x, y);
    l = __floats2bfloat162_rn(x - __low2float(h), y - __high2float(h));
}

#define AROW 40
#define BROWN 136

// ---------------------------------------------------------------------------
// Direct-LDG NT GEMM: no smem, no barriers. CTA = 64(M) x 256(N), 8 warps,
// each warp 64x32. 3-term bf16 split: Ah*Bh + Ah*Bl + Al*Bh.
// A[M,K], B[N,K] row-major (K contiguous) bf16 planes.
// Fragment layout (m16n8k16): A: a0={A[r][2c],A[r][2c+1]}, a1=+8 rows,
// a2=+8 cols, a3=both. B: b0={B[r][2c],B[r][2c+1]}, b1=+8 cols.
// Register double-buffered over k-steps of 16 (outer loop unrolled x2 so
// buffer index is compile-time).
// EPI 0: fp32*alpha -> C.  EPI 1: split bf16 -> Ch/Cl.
// ---------------------------------------------------------------------------
template<int EPI>
__device__ __forceinline__ void dl_core(
    const bf16* __restrict__ Ah, const bf16* __restrict__ Al, int lda,
    const bf16* __restrict__ Bh, const bf16* __restrict__ Bl, int ldb,
    float* __restrict__ C, bf16* __restrict__ Ch, bf16* __restrict__ Cl,
    int ldc, int K, float alpha)
{
    const int lane = threadIdx.x & 31;
    const int wid  = threadIdx.x >> 5;
    const int r    = lane >> 2;        // 0..7
    const int c2   = (lane & 3) << 1;  // 0,2,4,6

    // per-thread base pointers (warp n-offset folded into B)
    const bf16* a0h = Ah + (size_t)r * lda + c2;
    const bf16* a0l = Al + (size_t)r * lda + c2;
    const bf16* b0h = Bh + (size_t)(wid * 32 + r) * ldb + c2;
    const bf16* b0l = Bl + (size_t)(wid * 32 + r) * ldb + c2;

    uint32_t af[2][4][2][4];   // [buf][mt][plane][frag]
    uint32_t bg[2][4][2][2];   // [buf][nt][plane][frag]
    float acc[4][4][4];
#pragma unroll
    for (int i = 0; i < 4; ++i)
#pragma unroll
        for (int j = 0; j < 4; ++j)
#pragma unroll
            for (int l = 0; l < 4; ++l) acc[i][j][l] = 0.f;

    auto ldA = [&](int buf, int k) {
#pragma unroll
        for (int mt = 0; mt < 4; ++mt) {
            const bf16* ph = a0h + mt * 16 * lda + k;
            const bf16* pl = a0l + mt * 16 * lda + k;
            af[buf][mt][0][0] = *(const uint32_t*)(ph);
            af[buf][mt][0][1] = *(const uint32_t*)(ph + 8 * lda);
            af[buf][mt][0][2] = *(const uint32_t*)(ph + 8);
            af[buf][mt][0][3] = *(const uint32_t*)(ph + 8 * lda + 8);
            af[buf][mt][1][0] = *(const uint32_t*)(pl);
            af[buf][mt][1][1] = *(const uint32_t*)(pl + 8 * lda);
            af[buf][mt][1][2] = *(const uint32_t*)(pl + 8);
            af[buf][mt][1][3] = *(const uint32_t*)(pl + 8 * lda + 8);
        }
    };
    auto ldB = [&](int buf, int k) {
#pragma unroll
        for (int nt = 0; nt < 4; ++nt) {
            const bf16* ph = b0h + nt * 8 * ldb + k;
            const bf16* pl = b0l + nt * 8 * ldb + k;
            bg[buf][nt][0][0] = *(const uint32_t*)(ph);
            bg[buf][nt][0][1] = *(const uint32_t*)(ph + 8);
            bg[buf][nt][1][0] = *(const uint32_t*)(pl);
            bg[buf][nt][1][1] = *(const uint32_t*)(pl + 8);
        }
    };
    auto domma = [&](int buf) {
#pragma unroll
        for (int mt = 0; mt < 4; ++mt)
#pragma unroll
            for (int nt = 0; nt < 4; ++nt)
                mma_bf16(acc[mt][nt], af[buf][mt][0], bg[buf][nt][0]);  // h*h
#pragma unroll
        for (int mt = 0; mt < 4; ++mt)
#pragma unroll
            for (int nt = 0; nt < 4; ++nt)
                mma_bf16(acc[mt][nt], af[buf][mt][0], bg[buf][nt][1]);  // h*l
#pragma unroll
        for (int mt = 0; mt < 4; ++mt)
#pragma unroll
            for (int nt = 0; nt < 4; ++nt)
                mma_bf16(acc[mt][nt], af[buf][mt][1], bg[buf][nt][0]);  // l*h
    };

    const int nks = K >> 4;   // always even here (K = 2048 or 128)
    ldA(0, 0); ldB(0, 0);
#pragma unroll 1
    for (int ks = 0; ks < nks; ks += 2) {
        if (ks + 1 < nks) { ldA(1, (ks + 1) << 4); ldB(1, (ks + 1) << 4); }
        domma(0);
        if (ks + 2 < nks) { ldA(0, (ks + 2) << 4); ldB(0, (ks + 2) << 4); }
        if (ks + 1 < nks) domma(1);
    }

    // epilogue: warp writes its 64x32 tile at column offset wid*32
#pragma unroll
    for (int mt = 0; mt < 4; ++mt) {
#pragma unroll
        for (int nt = 0; nt < 4; ++nt) {
            int row = mt * 16 + r;
            int col = wid * 32 + nt * 8 + c2;
            if (EPI == 0) {
                float2 v0 = make_float2(alpha * acc[mt][nt][0], alpha * acc[mt][nt][1]);
                float2 v1 = make_float2(alpha * acc[mt][nt][2], alpha * acc[mt][nt][3]);
                *(float2*)&C[(size_t)row * ldc + col]       = v0;
                *(float2*)&C[(size_t)(row + 8) * ldc + col] = v1;
            } else {
                bf162 h0, l0, h1, l1;
                split2(acc[mt][nt][0], acc[mt][nt][1], h0, l0);
                split2(acc[mt][nt][2], acc[mt][nt][3], h1, l1);
                *(bf162*)&Ch[(size_t)row * ldc + col]       = h0;
                *(bf162*)&Cl[(size_t)row * ldc + col]       = l0;
                *(bf162*)&Ch[(size_t)(row + 8) * ldc + col] = h1;
                *(bf162*)&Cl[(size_t)(row + 8) * ldc + col] = l1;
            }
        }
    }
}

// ---------------- direct-LDG GEMM wrappers ----------------
__global__ __launch_bounds__(256) void dl_proj_f32(
    const bf16* __restrict__ Ah, const bf16* __restrict__ Al, int lda,
    const bf16* __restrict__ Bh, const bf16* __restrict__ Bl, int ldb,
    float* __restrict__ C, int ldc, int K)
{
    size_t ao = (size_t)blockIdx.y * 64 * lda;
    size_t bo = (size_t)blockIdx.x * 256 * ldb;
    dl_core<0>(Ah + ao, Al + ao, lda, Bh + bo, Bl + bo, ldb,
               C + (size_t)blockIdx.y * 64 * ldc + blockIdx.x * 256,
               nullptr, nullptr, ldc, K, 1.0f);
}

__global__ __launch_bounds__(256) void dl_proj_split(
    const bf16* __restrict__ Ah, const bf16* __restrict__ Al, int lda,
    const bf16* __restrict__ Bh, const bf16* __restrict__ Bl, int ldb,
    bf16* __restrict__ Ch, bf16* __restrict__ Cl, int ldc, int K)
{
    size_t ao = (size_t)blockIdx.y * 64 * lda;
    size_t bo = (size_t)blockIdx.x * 256 * ldb;
    size_t co = (size_t)blockIdx.y * 64 * ldc + blockIdx.x * 256;
    dl_core<1>(Ah + ao, Al + ao, lda, Bh + bo, Bl + bo, ldb,
               nullptr, Ch + co, Cl + co, ldc, K, 1.0f);
}

__global__ __launch_bounds__(256) void dl_score(
    const bf16* __restrict__ qh, const bf16* __restrict__ ql,
    const bf16* __restrict__ kh, const bf16* __restrict__ kl,
    float* __restrict__ attn)
{
    if (((int)blockIdx.x << 2) > (int)blockIdx.y) return;   // tile above diagonal
    const int bh = blockIdx.z;
    const int h = bh % HH, b = bh / HH, kv = h / GG;
    size_t ao = ((size_t)b * SS * HH + h) * HD + (size_t)blockIdx.y * 64 * (HH * HD);
    size_t bo = ((size_t)b * SS * KVH + kv) * HD + (size_t)blockIdx.x * 256 * (KVH * HD);
    float* C = attn + (size_t)bh * SS * SS
                    + (size_t)blockIdx.y * 64 * SS + (size_t)blockIdx.x * 256;
    dl_core<0>(qh + ao, ql + ao, HH * HD, kh + bo, kl + bo, KVH * HD,
               C, nullptr, nullptr, SS, HD, SCALE);
}

// ---------------------------------------------------------------------------
// AV: NN GEMM 128x128, A = fp32 attn (split inline), B = V planes, 3 terms.
// (unchanged from round 6 — passing)
// ---------------------------------------------------------------------------
__global__ __launch_bounds__(256, 2) void av_kernel(
    const float* __restrict__ attn, const bf16* __restrict__ Bhg,
    const bf16* __restrict__ Blg, bf16* __restrict__ Oh, bf16* __restrict__ Ol)
{
    const int bhz = blockIdx.z;
    const int h = bhz % HH, b = bhz / HH, kv = h / GG;
    const float* A = attn + (size_t)bhz * SS * SS + (size_t)blockIdx.y * 128 * SS;
    const bf16* Vh = Bhg + ((size_t)b * SS * KVH + kv) * HD;
    const bf16* Vl = Blg + ((size_t)b * SS * KVH + kv) * HD;
    bf16* Ch = Oh + ((size_t)b * SS * HH + h) * HD + (size_t)blockIdx.y * 128 * (HH * HD);
    bf16* Cl = Ol + ((size_t)b * SS * HH + h) * HD + (size_t)blockIdx.y * 128 * (HH * HD);
    const int lda = SS, ldb = KVH * HD, ldc = HH * HD;
    const int K = ((int)blockIdx.y + 1) * 128;

    __shared__ __align__(16) bf16 sAh[128 * AROW];
    __shared__ __align__(16) bf16 sAl[128 * AROW];
    __shared__ __align__(16) bf16 sBh[32 * BROWN];
    __shared__ __align__(16) bf16 sBl[32 * BROWN];

    const int tid  = threadIdx.x;
    const int lane = tid & 31;
    const int wid  = tid >> 5;
    const int wm   = (wid >> 2) << 6;
    const int wn   = (wid & 3) << 5;

    float acc[4][4][4];
#pragma unroll
    for (int i = 0; i < 4; ++i)
#pragma unroll
        for (int j = 0; j < 4; ++j)
#pragma unroll
            for (int l = 0; l < 4; ++l) acc[i][j][l] = 0.f;

    for (int k0 = 0; k0 < K; k0 += 32) {
        int task = tid;
#pragma unroll
        for (int p = 0; p < 4; ++p, task += 256) {
            int r = task >> 3, c4 = (task & 7) << 2;
            float4 v = *(const float4*)(A + (size_t)r * lda + k0 + c4);
            bf162 h0, l0, h1, l1;
            split2(v.x, v.y, h0, l0);
            split2(v.z, v.w, h1, l1);
            *(bf162*)&sAh[r * AROW + c4]     = h0;
            *(bf162*)&sAh[r * AROW + c4 + 2] = h1;
            *(bf162*)&sAl[r * AROW + c4]     = l0;
            *(bf162*)&sAl[r * AROW + c4 + 2] = l1;
        }
        task = tid;
#pragma unroll
        for (int p = 0; p < 2; ++p, task += 256) {
            int r = task >> 4, sg = (task & 15) << 3;
            *(uint4*)&sBh[r * BROWN + sg] = *(const uint4*)(Vh + (size_t)(k0 + r) * ldb + sg);
            *(uint4*)&sBl[r * BROWN + sg] = *(const uint4*)(Vl + (size_t)(k0 + r) * ldb + sg);
        }
        __syncthreads();

#pragma unroll
        for (int ks = 0; ks < 2; ++ks) {
            const int arow = lane & 15;
            const int akb  = ks * 32 + ((lane >> 4) << 4);
            uint32_t af[4][4], bh[4][2], bl[4][2];

#pragma unroll
            for (int mt = 0; mt < 4; ++mt)
                ldsm_x4(af[mt], smaddr(&sAh[(wm + mt * 16 + arow) * AROW]) + akb);
#pragma unroll
            for (int nt = 0; nt < 4; ++nt)
                ldsm_x2t(bh[nt], smaddr(&sBh[(ks * 16 + (lane & 15)) * BROWN + wn + nt * 8]));
#pragma unroll
            for (int mt = 0; mt < 4; ++mt)
#pragma unroll
                for (int nt = 0; nt < 4; ++nt) mma_bf16(acc[mt][nt], af[mt], bh[nt]);

#pragma unroll
            for (int nt = 0; nt < 4; ++nt)
                ldsm_x2t(bl[nt], smaddr(&sBl[(ks * 16 + (lane & 15)) * BROWN + wn + nt * 8]));
#pragma unroll
            for (int mt = 0; mt < 4; ++mt)
#pragma unroll
                for (int nt = 0; nt < 4; ++nt) mma_bf16(acc[mt][nt], af[mt], bl[nt]);

#pragma unroll
            for (int mt = 0; mt < 4; ++mt)
                ldsm_x4(af[mt], smaddr(&sAl[(wm + mt * 16 + arow) * AROW]) + akb);
#pragma unroll
            for (int mt = 0; mt < 4; ++mt)
#pragma unroll
                for (int nt = 0; nt < 4; ++nt) mma_bf16(acc[mt][nt], af[mt], bh[nt]);
        }
        __syncthreads();
    }

#pragma unroll
    for (int mt = 0; mt < 4; ++mt) {
#pragma unroll
        for (int nt = 0; nt < 4; ++nt) {
            int r = wm + mt * 16 + (lane >> 2);
            int c = wn + nt * 8 + ((lane & 3) << 1);
            bf162 h0, l0, h1, l1;
            split2(acc[mt][nt][0], acc[mt][nt][1], h0, l0);
            split2(acc[mt][nt][2], acc[mt][nt][3], h1, l1);
            *(bf162*)&Ch[(size_t)r * ldc + c]       = h0;
            *(bf162*)&Cl[(size_t)r * ldc + c]       = l0;
            *(bf162*)&Ch[(size_t)(r + 8) * ldc + c] = h1;
            *(bf162*)&Cl[(size_t)(r + 8) * ldc + c] = l1;
        }
    }
}

// ---------------- split fp32 -> bf16 hi/lo ----------------
__global__ __launch_bounds__(256) void split_kernel(
    const float* __restrict__ in, bf16* __restrict__ hi, bf16* __restrict__ lo, int n)
{
    int i = (blockIdx.x * 256 + threadIdx.x) * 4;
    if (i >= n) return;
    float4 v = *(const float4*)(in + i);
    bf162 h0, l0, h1, l1;
    split2(v.x, v.y, h0, l0);
    split2(v.z, v.w, h1, l1);
    *(bf162*)(hi + i)     = h0;
    *(bf162*)(hi + i + 2) = h1;
    *(bf162*)(lo + i)     = l0;
    *(bf162*)(lo + i + 2) = l1;
}

// ---------------- RMSNorm + RoPE -> split bf16 planes ----------------
__global__ __launch_bounds__(128) void normrope_split(
    const float* __restrict__ in, bf16* __restrict__ oh, bf16* __restrict__ ol,
    const float* __restrict__ w,
    const float* __restrict__ cosb, const float* __restrict__ sinb, int nheads)
{
    const int idx = blockIdx.x;
    const int h = idx % nheads;
    const int s = (idx / nheads) % SS;
    const int b = idx / (nheads * SS);
    const int t = threadIdx.x;

    size_t off = (((size_t)b * SS + s) * nheads + h) * HD;
    float v = in[off + t];

    float ss = v * v;
#pragma unroll
    for (int o = 16; o; o >>= 1) ss += __shfl_xor_sync(0xffffffffu, ss, o);

    __shared__ float ws[4];
    __shared__ float sh[128];
    const int lane = t & 31, wid = t >> 5;
    if (lane == 0) ws[wid] = ss;
    __syncthreads();
    float var = (ws[0] + ws[1] + ws[2] + ws[3]) * (1.0f / HD);
    float xn = v * rsqrtf(var + 1e-6f) * w[t];
    sh[t] = xn;
    __syncthreads();
    float rot = (t < 64) ? -sh[t + 64] : sh[t - 64];

    const float* cp = cosb + ((size_t)b * SS + s) * HD;
    const float* sp = sinb + ((size_t)b * SS + s) * HD;
    float r = xn * cp[t] + rot * sp[t];
    bf16 hh = __float2bfloat16(r);
    oh[off + t] = hh;
    ol[off + t] = __float2bfloat16(r - __bfloat162float(hh));
}

// ---------------- softmax (causal), fp32 in place ----------------
__global__ __launch_bounds__(256) void softmax_kernel(float* __restrict__ attn)
{
    __shared__ float buf[SS];
    __shared__ float red[256];
    const int row = blockIdx.x;
    const int qi = row & (SS - 1);
    const int valid = qi + 1;
    const int span = ((qi >> 7) + 1) << 7;
    float* base = attn + (size_t)row * SS;
    const int tid = threadIdx.x;

    float m = -1e30f;
    for (int t = tid * 4; t < span; t += 1024) {
        float4 v = *(const float4*)(base + t);
        v.x = (t + 0 < valid) ? v.x : -1e30f;
        v.y = (t + 1 < valid) ? v.y : -1e30f;
        v.z = (t + 2 < valid) ? v.z : -1e30f;
        v.w = (t + 3 < valid) ? v.w : -1e30f;
        *(float4*)(buf + t) = v;
        m = fmaxf(m, fmaxf(fmaxf(v.x, v.y), fmaxf(v.z, v.w)));
    }
    red[tid] = m; __syncthreads();
    for (int s2 = 128; s2; s2 >>= 1) {
        if (tid < s2) red[tid] = fmaxf(red[tid], red[tid + s2]);
        __syncthreads();
    }
    const float mx = red[0];
    __syncthreads();

    float sum = 0.f;
    for (int t = tid * 4; t < span; t += 1024) {
        float4 v = *(const float4*)(buf + t);
        v.x = expf(v.x - mx); v.y = expf(v.y - mx);
        v.z = expf(v.z - mx); v.w = expf(v.w - mx);
        *(float4*)(buf + t) = v;
        sum += v.x + v.y + v.z + v.w;
    }
    red[tid] = sum; __syncthreads();
    for (int s2 = 128; s2; s2 >>= 1) {
        if (tid < s2) red[tid] += red[tid + s2];
        __syncthreads();
    }
    const float inv = 1.0f / red[0];

    for (int t = tid * 4; t < SS; t += 1024) {
        float4 o;
        o.x = (t + 0 < span) ? buf[t + 0] * inv : 0.f;
        o.y = (t + 1 < span) ? buf[t + 1] * inv : 0.f;
        o.z = (t + 2 < span) ? buf[t + 2] * inv : 0.f;
        o.w = (t + 3 < span) ? buf[t + 3] * inv : 0.f;
        *(float4*)(base + t) = o;
    }
}

// ---------------- launch ----------------
extern "C" void kernel_launch(void* const* d_in, const int* in_sizes, int n_in,
                              void* d_out, int out_size)
{
    const float* x    = (const float*)d_in[0];
    const float* cosb = (const float*)d_in[1];
    const float* sinb = (const float*)d_in[2];
    const float* wq   = (const float*)d_in[4];
    const float* wk   = (const float*)d_in[5];
    const float* wv   = (const float*)d_in[6];
    const float* wo   = (const float*)d_in[7];
    const float* qw   = (const float*)d_in[8];
    const float* kw   = (const float*)d_in[9];

    float* out  = (float*)d_out;
    float* attn = out + (size_t)BB * SS * HH * HD;

    float *pq, *pk;
    bf16 *pxh, *pxl, *pwqh, *pwql, *pwkh, *pwkl, *pwvh, *pwvl, *pwoh, *pwol;
    bf16 *pqh, *pql, *pkh, *pkl, *pvh, *pvl, *poh, *pol;
    cudaGetSymbolAddress((void**)&pq, g_q);
    cudaGetSymbolAddress((void**)&pk, g_k);
    cudaGetSymbolAddress((void**)&pxh, xs_h);   cudaGetSymbolAddress((void**)&pxl, xs_l);
    cudaGetSymbolAddress((void**)&pwqh, wqs_h); cudaGetSymbolAddress((void**)&pwql, wqs_l);
    cudaGetSymbolAddress((void**)&pwkh, wks_h); cudaGetSymbolAddress((void**)&pwkl, wks_l);
    cudaGetSymbolAddress((void**)&pwvh, wvs_h); cudaGetSymbolAddress((void**)&pwvl, wvs_l);
    cudaGetSymbolAddress((void**)&pwoh, wos_h); cudaGetSymbolAddress((void**)&pwol, wos_l);
    cudaGetSymbolAddress((void**)&pqh, qs_h);   cudaGetSymbolAddress((void**)&pql, qs_l);
    cudaGetSymbolAddress((void**)&pkh, ks_h);   cudaGetSymbolAddress((void**)&pkl, ks_l);
    cudaGetSymbolAddress((void**)&pvh, vs_h);   cudaGetSymbolAddress((void**)&pvl, vs_l);
    cudaGetSymbolAddress((void**)&poh, os_h);   cudaGetSymbolAddress((void**)&pol, os_l);

    dim3 blk(256);

    // operand splits
    split_kernel<<<BB*SS*DD/1024, 256>>>(x,  pxh,  pxl,  BB*SS*DD);
    split_kernel<<<HH*HD*DD/1024, 256>>>(wq, pwqh, pwql, HH*HD*DD);
    split_kernel<<<KVH*HD*DD/1024, 256>>>(wk, pwkh, pwkl, KVH*HD*DD);
    split_kernel<<<KVH*HD*DD/1024, 256>>>(wv, pwvh, pwvl, KVH*HD*DD);
    split_kernel<<<DD*HH*HD/1024, 256>>>(wo, pwoh, pwol, DD*HH*HD);

    // projections (direct-LDG, grid = N/256 x M/64)
    dl_proj_f32<<<dim3((HH*HD)/256, (BB*SS)/64), blk>>>(
        pxh, pxl, DD, pwqh, pwql, DD, pq, HH*HD, DD);
    dl_proj_f32<<<dim3((KVH*HD)/256, (BB*SS)/64), blk>>>(
        pxh, pxl, DD, pwkh, pwkl, DD, pk, KVH*HD, DD);
    dl_proj_split<<<dim3((KVH*HD)/256, (BB*SS)/64), blk>>>(
        pxh, pxl, DD, pwvh, pwvl, DD, pvh, pvl, KVH*HD, DD);

    // norm + rope -> split planes
    normrope_split<<<BB*SS*HH, 128>>>(pq, pqh, pql, qw, cosb, sinb, HH);
    normrope_split<<<BB*SS*KVH, 128>>>(pk, pkh, pkl, kw, cosb, sinb, KVH);

    // attention
    dl_score<<<dim3(SS/256, SS/64, BB*HH), blk>>>(pqh, pql, pkh, pkl, attn);
    softmax_kernel<<<BB*HH*SS, 256>>>(attn);
    av_kernel<<<dim3(1, 16, BB*HH), blk>>>(attn, pvh, pvl, poh, pol);

    // output projection
    dl_proj_f32<<<dim3(DD/256, (BB*SS)/64), blk>>>(
        poh, pol, HH*HD, pwoh, pwol, HH*HD, out, DD, HH*HD);
}

// round 8
// speedup vs baseline: 2.1170x; 2.1170x over previous
#include <cuda_runtime.h>
#include <cuda_bf16.h>
#include <math.h>
#include <stdint.h>

#define BB   2
#define SS   2048
#define DD   2048
#define HH   16
#define KVH  8
#define GG   2
#define HD   128
#define SCALE 0.08838834764831845f

typedef __nv_bfloat16 bf16;
typedef __nv_bfloat162 bf162;

// ---------------- persistent scratch ----------------
__device__ float g_q[8388608];                     // (B,S,H,HD) fp32 pre-norm
__device__ float g_k[4194304];                     // (B,S,KV,HD)
__device__ bf16 xs_h[8388608],  xs_l[8388608];
__device__ bf16 wqs_h[4194304], wqs_l[4194304];
__device__ bf16 wks_h[2097152], wks_l[2097152];
__device__ bf16 wvs_h[2097152], wvs_l[2097152];
__device__ bf16 wos_h[4194304], wos_l[4194304];
__device__ bf16 qs_h[8388608],  qs_l[8388608];
__device__ bf16 ks_h[4194304],  ks_l[4194304];
__device__ bf16 vs_h[4194304],  vs_l[4194304];
__device__ bf16 os_h[8388608],  os_l[8388608];

// ---------------- PTX helpers ----------------
__device__ __forceinline__ uint32_t smaddr(const void* p) {
    return (uint32_t)__cvta_generic_to_shared(p);
}
__device__ __forceinline__ void cpa16(uint32_t d, const void* s) {
    asm volatile("cp.async.cg.shared.global [%0], [%1], 16;" :: "r"(d), "l"(s));
}
__device__ __forceinline__ void cp_commit() { asm volatile("cp.async.commit_group;"); }
__device__ __forceinline__ void cp_wait2()  { asm volatile("cp.async.wait_group 2;"); }
__device__ __forceinline__ void cp_wait1()  { asm volatile("cp.async.wait_group 1;"); }
__device__ __forceinline__ void cp_wait0()  { asm volatile("cp.async.wait_group 0;"); }

__device__ __forceinline__ void ldsm_x4(uint32_t* r, uint32_t addr) {
    asm volatile("ldmatrix.sync.aligned.m8n8.x4.shared.b16 {%0,%1,%2,%3}, [%4];"
        : "=r"(r[0]), "=r"(r[1]), "=r"(r[2]), "=r"(r[3]) : "r"(addr));
}
__device__ __forceinline__ void ldsm_x2(uint32_t* r, uint32_t addr) {
    asm volatile("ldmatrix.sync.aligned.m8n8.x2.shared.b16 {%0,%1}, [%2];"
        : "=r"(r[0]), "=r"(r[1]) : "r"(addr));
}
__device__ __forceinline__ void ldsm_x2t(uint32_t* r, uint32_t addr) {
    asm volatile("ldmatrix.sync.aligned.m8n8.x2.trans.shared.b16 {%0,%1}, [%2];"
        : "=r"(r[0]), "=r"(r[1]) : "r"(addr));
}
__device__ __forceinline__ void mma_bf16(float* c, const uint32_t* a, const uint32_t* b) {
    asm volatile(
        "mma.sync.aligned.m16n8k16.row.col.f32.bf16.bf16.f32 "
        "{%0,%1,%2,%3}, {%4,%5,%6,%7}, {%8,%9}, {%0,%1,%2,%3};"
        : "+f"(c[0]), "+f"(c[1]), "+f"(c[2]), "+f"(c[3])
        : "r"(a[0]), "r"(a[1]), "r"(a[2]), "r"(a[3]), "r"(b[0]), "r"(b[1]));
}
__device__ __forceinline__ void split2(float x, float y, bf162& h, bf162& l) {
    h = __floats2bfloat162_rn(x, y);
    l = __floats2bfloat162_rn(x - __low2float(h), y - __high2float(h));
}

#define AR16 24     // 16 K-elems + 8 pad -> 48B row stride (conflict-free ldsm)
#define AROW 40
#define BROWN 136

// ---------------------------------------------------------------------------
// NT GEMM, 128x128 CTA tile, 8 warps of 64x32, 3-term bf16 split.
// 4-stage cp.async pipeline, Kc=16 per stage, prefetch distance 2,
// ONE __syncthreads per chunk (race-free with 4 buffers at warp skew <=1).
// A[M,K] x B[N,K]^T, pre-split K-major bf16 planes.
// EPI 0: fp32*alpha -> C.  EPI 1: split bf16 -> Ch/Cl.
// Dynamic smem: 4 stages x 24576 B = 98304 B. 2 CTAs/SM.
// ---------------------------------------------------------------------------
template<int EPI>
__device__ __forceinline__ void nt_core(
    const bf16* __restrict__ Ah, const bf16* __restrict__ Al, int lda,
    const bf16* __restrict__ Bh, const bf16* __restrict__ Bl, int ldb,
    float* __restrict__ C, bf16* __restrict__ Ch, bf16* __restrict__ Cl,
    int ldc, int K, float alpha)
{
    extern __shared__ __align__(16) bf16 sm[];
    constexpr int PL  = 128 * AR16;   // 3072 elems per plane
    constexpr int STG = 4 * PL;       // 12288 elems = 24576 B per stage

    const int tid  = threadIdx.x;
    const int lane = tid & 31;
    const int wid  = tid >> 5;
    const int wm   = (wid >> 2) << 6;   // 0 or 64
    const int wn   = (wid & 3) << 5;    // 0,32,64,96

    float acc[4][4][4];
#pragma unroll
    for (int i = 0; i < 4; ++i)
#pragma unroll
        for (int j = 0; j < 4; ++j)
#pragma unroll
            for (int l = 0; l < 4; ++l) acc[i][j][l] = 0.f;

    const int row  = tid >> 1;           // 0..127
    const int half = tid & 1;            // 16B half of the 32B row
    const int eo   = row * AR16 + half * 8;

    auto stage = [&](int buf, int k0) {
        bf16* b = sm + buf * STG;
        size_t ga = (size_t)row * lda + k0 + half * 8;
        size_t gb = (size_t)row * ldb + k0 + half * 8;
        cpa16(smaddr(b + eo),          Ah + ga);
        cpa16(smaddr(b + PL + eo),     Al + ga);
        cpa16(smaddr(b + 2 * PL + eo), Bh + gb);
        cpa16(smaddr(b + 3 * PL + eo), Bl + gb);
        cp_commit();
    };

    const int nch = K >> 4;
    stage(0, 0);
    stage(1, 16);
#pragma unroll 1
    for (int i = 0; i < nch; ++i) {
        if (i + 2 < nch)      { stage((i + 2) & 3, (i + 2) << 4); cp_wait2(); }
        else if (i + 1 < nch) cp_wait1();
        else                  cp_wait0();
        __syncthreads();

        const bf16* pAh = sm + (i & 3) * STG;
        const bf16* pAl = pAh + PL;
        const bf16* pBh = pAh + 2 * PL;
        const bf16* pBl = pAh + 3 * PL;

        const int aoff = ((lane >> 4)) << 4;          // 0 or 16 bytes
        const int boff = ((lane >> 3) & 1) << 4;
        uint32_t ah[4][4], al[4][4], bh[4][2], bl[4][2];

#pragma unroll
        for (int mt = 0; mt < 4; ++mt)
            ldsm_x4(ah[mt], smaddr(pAh + (wm + mt * 16 + (lane & 15)) * AR16) + aoff);
#pragma unroll
        for (int nt = 0; nt < 4; ++nt)
            ldsm_x2(bh[nt], smaddr(pBh + (wn + nt * 8 + (lane & 7)) * AR16) + boff);
#pragma unroll
        for (int mt = 0; mt < 4; ++mt)
#pragma unroll
            for (int nt = 0; nt < 4; ++nt) mma_bf16(acc[mt][nt], ah[mt], bh[nt]);

#pragma unroll
        for (int nt = 0; nt < 4; ++nt)
            ldsm_x2(bl[nt], smaddr(pBl + (wn + nt * 8 + (lane & 7)) * AR16) + boff);
#pragma unroll
        for (int mt = 0; mt < 4; ++mt)
#pragma unroll
            for (int nt = 0; nt < 4; ++nt) mma_bf16(acc[mt][nt], ah[mt], bl[nt]);

#pragma unroll
        for (int mt = 0; mt < 4; ++mt)
            ldsm_x4(al[mt], smaddr(pAl + (wm + mt * 16 + (lane & 15)) * AR16) + aoff);
#pragma unroll
        for (int mt = 0; mt < 4; ++mt)
#pragma unroll
            for (int nt = 0; nt < 4; ++nt) mma_bf16(acc[mt][nt], al[mt], bh[nt]);
    }

#pragma unroll
    for (int mt = 0; mt < 4; ++mt) {
#pragma unroll
        for (int nt = 0; nt < 4; ++nt) {
            int r = wm + mt * 16 + (lane >> 2);
            int c = wn + nt * 8 + ((lane & 3) << 1);
            if (EPI == 0) {
                float2 v0 = make_float2(alpha * acc[mt][nt][0], alpha * acc[mt][nt][1]);
                float2 v1 = make_float2(alpha * acc[mt][nt][2], alpha * acc[mt][nt][3]);
                *(float2*)&C[(size_t)r * ldc + c]       = v0;
                *(float2*)&C[(size_t)(r + 8) * ldc + c] = v1;
            } else {
                bf162 h0, l0, h1, l1;
                split2(acc[mt][nt][0], acc[mt][nt][1], h0, l0);
                split2(acc[mt][nt][2], acc[mt][nt][3], h1, l1);
                *(bf162*)&Ch[(size_t)r * ldc + c]       = h0;
                *(bf162*)&Cl[(size_t)r * ldc + c]       = l0;
                *(bf162*)&Ch[(size_t)(r + 8) * ldc + c] = h1;
                *(bf162*)&Cl[(size_t)(r + 8) * ldc + c] = l1;
            }
        }
    }
}

#define SMNT 98304

__global__ __launch_bounds__(256, 2) void proj_f32_k(
    const bf16* __restrict__ Ah, const bf16* __restrict__ Al, int lda,
    const bf16* __restrict__ Bh, const bf16* __restrict__ Bl, int ldb,
    float* __restrict__ C, int ldc, int K)
{
    size_t ao = (size_t)blockIdx.y * 128 * lda;
    size_t bo = (size_t)blockIdx.x * 128 * ldb;
    nt_core<0>(Ah + ao, Al + ao, lda, Bh + bo, Bl + bo, ldb,
               C + (size_t)blockIdx.y * 128 * ldc + blockIdx.x * 128,
               nullptr, nullptr, ldc, K, 1.0f);
}

__global__ __launch_bounds__(256, 2) void proj_split_k(
    const bf16* __restrict__ Ah, const bf16* __restrict__ Al, int lda,
    const bf16* __restrict__ Bh, const bf16* __restrict__ Bl, int ldb,
    bf16* __restrict__ Ch, bf16* __restrict__ Cl, int ldc, int K)
{
    size_t ao = (size_t)blockIdx.y * 128 * lda;
    size_t bo = (size_t)blockIdx.x * 128 * ldb;
    size_t co = (size_t)blockIdx.y * 128 * ldc + blockIdx.x * 128;
    nt_core<1>(Ah + ao, Al + ao, lda, Bh + bo, Bl + bo, ldb,
               nullptr, Ch + co, Cl + co, ldc, K, 1.0f);
}

__global__ __launch_bounds__(256, 2) void score_k(
    const bf16* __restrict__ qh, const bf16* __restrict__ ql,
    const bf16* __restrict__ kh, const bf16* __restrict__ kl,
    float* __restrict__ attn)
{
    if (blockIdx.x > blockIdx.y) return;   // tile above causal diagonal
    const int bh = blockIdx.z;
    const int h = bh % HH, b = bh / HH, kv = h / GG;
    size_t ao = ((size_t)b * SS * HH + h) * HD + (size_t)blockIdx.y * 128 * (HH * HD);
    size_t bo = ((size_t)b * SS * KVH + kv) * HD + (size_t)blockIdx.x * 128 * (KVH * HD);
    float* C = attn + (size_t)bh * SS * SS
                    + (size_t)blockIdx.y * 128 * SS + (size_t)blockIdx.x * 128;
    nt_core<0>(qh + ao, ql + ao, HH * HD, kh + bo, kl + bo, KVH * HD,
               C, nullptr, nullptr, SS, HD, SCALE);
}

// ---------------------------------------------------------------------------
// AV: NN GEMM 128x128, A = fp32 attn (split inline), B = V planes, 3 terms.
// (round-6 passing version, unchanged)
// ---------------------------------------------------------------------------
__global__ __launch_bounds__(256, 2) void av_kernel(
    const float* __restrict__ attn, const bf16* __restrict__ Bhg,
    const bf16* __restrict__ Blg, bf16* __restrict__ Oh, bf16* __restrict__ Ol)
{
    const int bhz = blockIdx.z;
    const int h = bhz % HH, b = bhz / HH, kv = h / GG;
    const float* A = attn + (size_t)bhz * SS * SS + (size_t)blockIdx.y * 128 * SS;
    const bf16* Vh = Bhg + ((size_t)b * SS * KVH + kv) * HD;
    const bf16* Vl = Blg + ((size_t)b * SS * KVH + kv) * HD;
    bf16* Ch = Oh + ((size_t)b * SS * HH + h) * HD + (size_t)blockIdx.y * 128 * (HH * HD);
    bf16* Cl = Ol + ((size_t)b * SS * HH + h) * HD + (size_t)blockIdx.y * 128 * (HH * HD);
    const int lda = SS, ldb = KVH * HD, ldc = HH * HD;
    const int K = ((int)blockIdx.y + 1) * 128;

    __shared__ __align__(16) bf16 sAh[128 * AROW];
    __shared__ __align__(16) bf16 sAl[128 * AROW];
    __shared__ __align__(16) bf16 sBh[32 * BROWN];
    __shared__ __align__(16) bf16 sBl[32 * BROWN];

    const int tid  = threadIdx.x;
    const int lane = tid & 31;
    const int wid  = tid >> 5;
    const int wm   = (wid >> 2) << 6;
    const int wn   = (wid & 3) << 5;

    float acc[4][4][4];
#pragma unroll
    for (int i = 0; i < 4; ++i)
#pragma unroll
        for (int j = 0; j < 4; ++j)
#pragma unroll
            for (int l = 0; l < 4; ++l) acc[i][j][l] = 0.f;

    for (int k0 = 0; k0 < K; k0 += 32) {
        int task = tid;
#pragma unroll
        for (int p = 0; p < 4; ++p, task += 256) {
            int r = task >> 3, c4 = (task & 7) << 2;
            float4 v = *(const float4*)(A + (size_t)r * lda + k0 + c4);
            bf162 h0, l0, h1, l1;
            split2(v.x, v.y, h0, l0);
            split2(v.z, v.w, h1, l1);
            *(bf162*)&sAh[r * AROW + c4]     = h0;
            *(bf162*)&sAh[r * AROW + c4 + 2] = h1;
            *(bf162*)&sAl[r * AROW + c4]     = l0;
            *(bf162*)&sAl[r * AROW + c4 + 2] = l1;
        }
        task = tid;
#pragma unroll
        for (int p = 0; p < 2; ++p, task += 256) {
            int r = task >> 4, sg = (task & 15) << 3;
            *(uint4*)&sBh[r * BROWN + sg] = *(const uint4*)(Vh + (size_t)(k0 + r) * ldb + sg);
            *(uint4*)&sBl[r * BROWN + sg] = *(const uint4*)(Vl + (size_t)(k0 + r) * ldb + sg);
        }
        __syncthreads();

#pragma unroll
        for (int ks = 0; ks < 2; ++ks) {
            const int arow = lane & 15;
            const int akb  = ks * 32 + ((lane >> 4) << 4);
            uint32_t af[4][4], bh[4][2], bl[4][2];

#pragma unroll
            for (int mt = 0; mt < 4; ++mt)
                ldsm_x4(af[mt], smaddr(&sAh[(wm + mt * 16 + arow) * AROW]) + akb);
#pragma unroll
            for (int nt = 0; nt < 4; ++nt)
                ldsm_x2t(bh[nt], smaddr(&sBh[(ks * 16 + (lane & 15)) * BROWN + wn + nt * 8]));
#pragma unroll
            for (int mt = 0; mt < 4; ++mt)
#pragma unroll
                for (int nt = 0; nt < 4; ++nt) mma_bf16(acc[mt][nt], af[mt], bh[nt]);

#pragma unroll
            for (int nt = 0; nt < 4; ++nt)
                ldsm_x2t(bl[nt], smaddr(&sBl[(ks * 16 + (lane & 15)) * BROWN + wn + nt * 8]));
#pragma unroll
            for (int mt = 0; mt < 4; ++mt)
#pragma unroll
                for (int nt = 0; nt < 4; ++nt) mma_bf16(acc[mt][nt], af[mt], bl[nt]);

#pragma unroll
            for (int mt = 0; mt < 4; ++mt)
                ldsm_x4(af[mt], smaddr(&sAl[(wm + mt * 16 + arow) * AROW]) + akb);
#pragma unroll
            for (int mt = 0; mt < 4; ++mt)
#pragma unroll
                for (int nt = 0; nt < 4; ++nt) mma_bf16(acc[mt][nt], af[mt], bh[nt]);
        }
        __syncthreads();
    }

#pragma unroll
    for (int mt = 0; mt < 4; ++mt) {
#pragma unroll
        for (int nt = 0; nt < 4; ++nt) {
            int r = wm + mt * 16 + (lane >> 2);
            int c = wn + nt * 8 + ((lane & 3) << 1);
            bf162 h0, l0, h1, l1;
            split2(acc[mt][nt][0], acc[mt][nt][1], h0, l0);
            split2(acc[mt][nt][2], acc[mt][nt][3], h1, l1);
            *(bf162*)&Ch[(size_t)r * ldc + c]       = h0;
            *(bf162*)&Cl[(size_t)r * ldc + c]       = l0;
            *(bf162*)&Ch[(size_t)(r + 8) * ldc + c] = h1;
            *(bf162*)&Cl[(size_t)(r + 8) * ldc + c] = l1;
        }
    }
}

// ---------------- split fp32 -> bf16 hi/lo ----------------
__global__ __launch_bounds__(256) void split_kernel(
    const float* __restrict__ in, bf16* __restrict__ hi, bf16* __restrict__ lo, int n)
{
    int i = (blockIdx.x * 256 + threadIdx.x) * 4;
    if (i >= n) return;
    float4 v = *(const float4*)(in + i);
    bf162 h0, l0, h1, l1;
    split2(v.x, v.y, h0, l0);
    split2(v.z, v.w, h1, l1);
    *(bf162*)(hi + i)     = h0;
    *(bf162*)(hi + i + 2) = h1;
    *(bf162*)(lo + i)     = l0;
    *(bf162*)(lo + i + 2) = l1;
}

// ---------------- RMSNorm + RoPE -> split bf16 planes ----------------
__global__ __launch_bounds__(128) void normrope_split(
    const float* __restrict__ in, bf16* __restrict__ oh, bf16* __restrict__ ol,
    const float* __restrict__ w,
    const float* __restrict__ cosb, const float* __restrict__ sinb, int nheads)
{
    const int idx = blockIdx.x;
    const int h = idx % nheads;
    const int s = (idx / nheads) % SS;
    const int b = idx / (nheads * SS);
    const int t = threadIdx.x;

    size_t off = (((size_t)b * SS + s) * nheads + h) * HD;
    float v = in[off + t];

    float ss = v * v;
#pragma unroll
    for (int o = 16; o; o >>= 1) ss += __shfl_xor_sync(0xffffffffu, ss, o);

    __shared__ float ws[4];
    __shared__ float sh[128];
    const int lane = t & 31, wid = t >> 5;
    if (lane == 0) ws[wid] = ss;
    __syncthreads();
    float var = (ws[0] + ws[1] + ws[2] + ws[3]) * (1.0f / HD);
    float xn = v * rsqrtf(var + 1e-6f) * w[t];
    sh[t] = xn;
    __syncthreads();
    float rot = (t < 64) ? -sh[t + 64] : sh[t - 64];

    const float* cp = cosb + ((size_t)b * SS + s) * HD;
    const float* sp = sinb + ((size_t)b * SS + s) * HD;
    float r = xn * cp[t] + rot * sp[t];
    bf16 hh = __float2bfloat16(r);
    oh[off + t] = hh;
    ol[off + t] = __float2bfloat16(r - __bfloat162float(hh));
}

// ---------------- softmax (causal), fp32 in place ----------------
__global__ __launch_bounds__(256) void softmax_kernel(float* __restrict__ attn)
{
    __shared__ float buf[SS];
    __shared__ float red[256];
    const int row = blockIdx.x;
    const int qi = row & (SS - 1);
    const int valid = qi + 1;
    const int span = ((qi >> 7) + 1) << 7;
    float* base = attn + (size_t)row * SS;
    const int tid = threadIdx.x;

    float m = -1e30f;
    for (int t = tid * 4; t < span; t += 1024) {
        float4 v = *(const float4*)(base + t);
        v.x = (t + 0 < valid) ? v.x : -1e30f;
        v.y = (t + 1 < valid) ? v.y : -1e30f;
        v.z = (t + 2 < valid) ? v.z : -1e30f;
        v.w = (t + 3 < valid) ? v.w : -1e30f;
        *(float4*)(buf + t) = v;
        m = fmaxf(m, fmaxf(fmaxf(v.x, v.y), fmaxf(v.z, v.w)));
    }
    red[tid] = m; __syncthreads();
    for (int s2 = 128; s2; s2 >>= 1) {
        if (tid < s2) red[tid] = fmaxf(red[tid], red[tid + s2]);
        __syncthreads();
    }
    const float mx = red[0];
    __syncthreads();

    float sum = 0.f;
    for (int t = tid * 4; t < span; t += 1024) {
        float4 v = *(const float4*)(buf + t);
        v.x = expf(v.x - mx); v.y = expf(v.y - mx);
        v.z = expf(v.z - mx); v.w = expf(v.w - mx);
        *(float4*)(buf + t) = v;
        sum += v.x + v.y + v.z + v.w;
    }
    red[tid] = sum; __syncthreads();
    for (int s2 = 128; s2; s2 >>= 1) {
        if (tid < s2) red[tid] += red[tid + s2];
        __syncthreads();
    }
    const float inv = 1.0f / red[0];

    for (int t = tid * 4; t < SS; t += 1024) {
        float4 o;
        o.x = (t + 0 < span) ? buf[t + 0] * inv : 0.f;
        o.y = (t + 1 < span) ? buf[t + 1] * inv : 0.f;
        o.z = (t + 2 < span) ? buf[t + 2] * inv : 0.f;
        o.w = (t + 3 < span) ? buf[t + 3] * inv : 0.f;
        *(float4*)(base + t) = o;
    }
}

// ---------------- launch ----------------
extern "C" void kernel_launch(void* const* d_in, const int* in_sizes, int n_in,
                              void* d_out, int out_size)
{
    const float* x    = (const float*)d_in[0];
    const float* cosb = (const float*)d_in[1];
    const float* sinb = (const float*)d_in[2];
    const float* wq   = (const float*)d_in[4];
    const float* wk   = (const float*)d_in[5];
    const float* wv   = (const float*)d_in[6];
    const float* wo   = (const float*)d_in[7];
    const float* qw   = (const float*)d_in[8];
    const float* kw   = (const float*)d_in[9];

    float* out  = (float*)d_out;
    float* attn = out + (size_t)BB * SS * HH * HD;

    float *pq, *pk;
    bf16 *pxh, *pxl, *pwqh, *pwql, *pwkh, *pwkl, *pwvh, *pwvl, *pwoh, *pwol;
    bf16 *pqh, *pql, *pkh, *pkl, *pvh, *pvl, *poh, *pol;
    cudaGetSymbolAddress((void**)&pq, g_q);
    cudaGetSymbolAddress((void**)&pk, g_k);
    cudaGetSymbolAddress((void**)&pxh, xs_h);   cudaGetSymbolAddress((void**)&pxl, xs_l);
    cudaGetSymbolAddress((void**)&pwqh, wqs_h); cudaGetSymbolAddress((void**)&pwql, wqs_l);
    cudaGetSymbolAddress((void**)&pwkh, wks_h); cudaGetSymbolAddress((void**)&pwkl, wks_l);
    cudaGetSymbolAddress((void**)&pwvh, wvs_h); cudaGetSymbolAddress((void**)&pwvl, wvs_l);
    cudaGetSymbolAddress((void**)&pwoh, wos_h); cudaGetSymbolAddress((void**)&pwol, wos_l);
    cudaGetSymbolAddress((void**)&pqh, qs_h);   cudaGetSymbolAddress((void**)&pql, qs_l);
    cudaGetSymbolAddress((void**)&pkh, ks_h);   cudaGetSymbolAddress((void**)&pkl, ks_l);
    cudaGetSymbolAddress((void**)&pvh, vs_h);   cudaGetSymbolAddress((void**)&pvl, vs_l);
    cudaGetSymbolAddress((void**)&poh, os_h);   cudaGetSymbolAddress((void**)&pol, os_l);

    cudaFuncSetAttribute(proj_f32_k,  cudaFuncAttributeMaxDynamicSharedMemorySize, SMNT);
    cudaFuncSetAttribute(proj_split_k,cudaFuncAttributeMaxDynamicSharedMemorySize, SMNT);
    cudaFuncSetAttribute(score_k,     cudaFuncAttributeMaxDynamicSharedMemorySize, SMNT);

    const int BS = BB * SS;   // 4096
    dim3 blk(256);

    // splits first (indices 0-4) so capture index 5 = Q projection GEMM
    split_kernel<<<BB*SS*DD/1024, 256>>>(x,  pxh,  pxl,  BB*SS*DD);
    split_kernel<<<HH*HD*DD/1024, 256>>>(wq, pwqh, pwql, HH*HD*DD);
    split_kernel<<<KVH*HD*DD/1024, 256>>>(wk, pwkh, pwkl, KVH*HD*DD);
    split_kernel<<<KVH*HD*DD/1024, 256>>>(wv, pwvh, pwvl, KVH*HD*DD);
    split_kernel<<<DD*HH*HD/1024, 256>>>(wo, pwoh, pwol, DD*HH*HD);

    proj_f32_k<<<dim3((HH*HD)/128, BS/128), blk, SMNT>>>(
        pxh, pxl, DD, pwqh, pwql, DD, pq, HH*HD, DD);
    proj_f32_k<<<dim3((KVH*HD)/128, BS/128), blk, SMNT>>>(
        pxh, pxl, DD, pwkh, pwkl, DD, pk, KVH*HD, DD);
    proj_split_k<<<dim3((KVH*HD)/128, BS/128), blk, SMNT>>>(
        pxh, pxl, DD, pwvh, pwvl, DD, pvh, pvl, KVH*HD, DD);

    normrope_split<<<BB*SS*HH, 128>>>(pq, pqh, pql, qw, cosb, sinb, HH);
    normrope_split<<<BB*SS*KVH, 128>>>(pk, pkh, pkl, kw, cosb, sinb, KVH);

    score_k<<<dim3(SS/128, SS/128, BB*HH), blk, SMNT>>>(pqh, pql, pkh, pkl, attn);
    softmax_kernel<<<BB*HH*SS, 256>>>(attn);
    av_kernel<<<dim3(1, 16, BB*HH), blk>>>(attn, pvh, pvl, poh, pol);

    proj_f32_k<<<dim3(DD/128, BS/128), blk, SMNT>>>(
        poh, pol, HH*HD, pwoh, pwol, HH*HD, out, DD, HH*HD);
}

// round 9
// speedup vs baseline: 2.2105x; 1.0441x over previous
#include <cuda_runtime.h>
#include <cuda_bf16.h>
#include <math.h>
#include <stdint.h>

#define BB   2
#define SS   2048
#define DD   2048
#define HH   16
#define KVH  8
#define GG   2
#define HD   128
#define SCALE 0.08838834764831845f

typedef __nv_bfloat16 bf16;
typedef __nv_bfloat162 bf162;

// ---------------- persistent scratch (fp32, as in the 1639.8 baseline) ----
__device__ float g_q[(size_t)BB * SS * HH  * HD];   // (B,S,H,HD)
__device__ float g_k[(size_t)BB * SS * KVH * HD];   // (B,S,KV,HD)
__device__ float g_v[(size_t)BB * SS * KVH * HD];   // (B,S,KV,HD)
__device__ float g_o[(size_t)BB * SS * HH  * HD];   // (B,S,H,HD)

// ---------------- PTX helpers ----------------
__device__ __forceinline__ uint32_t smaddr(const void* p) {
    return (uint32_t)__cvta_generic_to_shared(p);
}
__device__ __forceinline__ void ldsm_x4(uint32_t* r, uint32_t addr) {
    asm volatile("ldmatrix.sync.aligned.m8n8.x4.shared.b16 {%0,%1,%2,%3}, [%4];"
        : "=r"(r[0]), "=r"(r[1]), "=r"(r[2]), "=r"(r[3]) : "r"(addr));
}
__device__ __forceinline__ void ldsm_x2(uint32_t* r, uint32_t addr) {
    asm volatile("ldmatrix.sync.aligned.m8n8.x2.shared.b16 {%0,%1}, [%2];"
        : "=r"(r[0]), "=r"(r[1]) : "r"(addr));
}
__device__ __forceinline__ void ldsm_x2t(uint32_t* r, uint32_t addr) {
    asm volatile("ldmatrix.sync.aligned.m8n8.x2.trans.shared.b16 {%0,%1}, [%2];"
        : "=r"(r[0]), "=r"(r[1]) : "r"(addr));
}
__device__ __forceinline__ void mma_bf16(float* c, const uint32_t* a, const uint32_t* b) {
    asm volatile(
        "mma.sync.aligned.m16n8k16.row.col.f32.bf16.bf16.f32 "
        "{%0,%1,%2,%3}, {%4,%5,%6,%7}, {%8,%9}, {%0,%1,%2,%3};"
        : "+f"(c[0]), "+f"(c[1]), "+f"(c[2]), "+f"(c[3])
        : "r"(a[0]), "r"(a[1]), "r"(a[2]), "r"(a[3]), "r"(b[0]), "r"(b[1]));
}

// ---------------------------------------------------------------------------
// bf16x3 split GEMM core (EXACT 1639.8-µs baseline core).
// C[128,128] tile of A[M,K] (row-major) times:
//   BTRANS=true : B[N,K] row-major (NT) ->  C = A * B^T
//   BTRANS=false: B[K,N] row-major (NN) ->  C = A * B
// Caller pre-offsets A, B, C to the tile origin. 256 threads, 2 CTAs/SM.
// Each fp32 operand is split hi+lo (bf16); product = hi*hi + hi*lo + lo*hi.
// ---------------------------------------------------------------------------
#define AROW 40
#define BROWN 136

template<bool BTRANS>
__device__ __forceinline__ void gemm_core(
    const float* __restrict__ A, int lda,
    const float* __restrict__ B, int ldb,
    float* __restrict__ C, int ldc, int K, float alpha)
{
    __shared__ __align__(16) __nv_bfloat16 sAh[128 * AROW];
    __shared__ __align__(16) __nv_bfloat16 sAl[128 * AROW];
    __shared__ __align__(16) __nv_bfloat16 sBh[5120];
    __shared__ __align__(16) __nv_bfloat16 sBl[5120];

    const int tid  = threadIdx.x;
    const int lane = tid & 31;
    const int wid  = tid >> 5;
    const int wm   = (wid >> 2) << 6;   // 0 or 64
    const int wn   = (wid & 3) << 5;    // 0,32,64,96

    float acc[4][4][4];
#pragma unroll
    for (int i = 0; i < 4; ++i)
#pragma unroll
        for (int j = 0; j < 4; ++j)
#pragma unroll
            for (int l = 0; l < 4; ++l) acc[i][j][l] = 0.f;

    for (int k0 = 0; k0 < K; k0 += 32) {
        // ---- stage A tile (128 x 32) with hi/lo split ----
        {
            int r = tid >> 3;
            const int c = (tid & 7) << 2;
#pragma unroll
            for (int p = 0; p < 4; ++p, r += 32) {
                float4 v = *(const float4*)(A + (size_t)r * lda + k0 + c);
                __nv_bfloat162 H0 = __floats2bfloat162_rn(v.x, v.y);
                __nv_bfloat162 H1 = __floats2bfloat162_rn(v.z, v.w);
                __nv_bfloat162 L0 = __floats2bfloat162_rn(v.x - __low2float(H0),
                                                          v.y - __high2float(H0));
                __nv_bfloat162 L1 = __floats2bfloat162_rn(v.z - __low2float(H1),
                                                          v.w - __high2float(H1));
                *(__nv_bfloat162*)&sAh[r * AROW + c]     = H0;
                *(__nv_bfloat162*)&sAh[r * AROW + c + 2] = H1;
                *(__nv_bfloat162*)&sAl[r * AROW + c]     = L0;
                *(__nv_bfloat162*)&sAl[r * AROW + c + 2] = L1;
            }
        }
        // ---- stage B tile with hi/lo split ----
        if (BTRANS) {
            int r = tid >> 3;
            const int c = (tid & 7) << 2;
#pragma unroll
            for (int p = 0; p < 4; ++p, r += 32) {
                float4 v = *(const float4*)(B + (size_t)r * ldb + k0 + c);
                __nv_bfloat162 H0 = __floats2bfloat162_rn(v.x, v.y);
                __nv_bfloat162 H1 = __floats2bfloat162_rn(v.z, v.w);
                __nv_bfloat162 L0 = __floats2bfloat162_rn(v.x - __low2float(H0),
                                                          v.y - __high2float(H0));
                __nv_bfloat162 L1 = __floats2bfloat162_rn(v.z - __low2float(H1),
                                                          v.w - __high2float(H1));
                *(__nv_bfloat162*)&sBh[r * AROW + c]     = H0;
                *(__nv_bfloat162*)&sBh[r * AROW + c + 2] = H1;
                *(__nv_bfloat162*)&sBl[r * AROW + c]     = L0;
                *(__nv_bfloat162*)&sBl[r * AROW + c + 2] = L1;
            }
        } else {
            int r = tid >> 5;
            const int c = (tid & 31) << 2;
#pragma unroll
            for (int p = 0; p < 4; ++p, r += 8) {
                float4 v = *(const float4*)(B + (size_t)(k0 + r) * ldb + c);
                __nv_bfloat162 H0 = __floats2bfloat162_rn(v.x, v.y);
                __nv_bfloat162 H1 = __floats2bfloat162_rn(v.z, v.w);
                __nv_bfloat162 L0 = __floats2bfloat162_rn(v.x - __low2float(H0),
                                                          v.y - __high2float(H0));
                __nv_bfloat162 L1 = __floats2bfloat162_rn(v.z - __low2float(H1),
                                                          v.w - __high2float(H1));
                *(__nv_bfloat162*)&sBh[r * BROWN + c]     = H0;
                *(__nv_bfloat162*)&sBh[r * BROWN + c + 2] = H1;
                *(__nv_bfloat162*)&sBl[r * BROWN + c]     = L0;
                *(__nv_bfloat162*)&sBl[r * BROWN + c + 2] = L1;
            }
        }
        __syncthreads();

#pragma unroll
        for (int ks = 0; ks < 2; ++ks) {
            uint32_t af[4][4];
            uint32_t bh[4][2];
            uint32_t bl[4][2];

            const int arow_off = (lane & 15);
            const int akb = ks * 32 + ((lane >> 4) << 4);

            // A hi fragments
#pragma unroll
            for (int mt = 0; mt < 4; ++mt)
                ldsm_x4(af[mt], smaddr(&sAh[(wm + mt * 16 + arow_off) * AROW]) + akb);

            // B hi fragments
#pragma unroll
            for (int nt = 0; nt < 4; ++nt) {
                if (BTRANS) {
                    uint32_t ad = smaddr(&sBh[(wn + nt * 8 + (lane & 7)) * AROW])
                                + ks * 32 + (((lane >> 3) & 1) << 4);
                    ldsm_x2(bh[nt], ad);
                } else {
                    uint32_t ad = smaddr(&sBh[(ks * 16 + (lane & 15)) * BROWN + wn + nt * 8]);
                    ldsm_x2t(bh[nt], ad);
                }
            }
#pragma unroll
            for (int mt = 0; mt < 4; ++mt)
#pragma unroll
                for (int nt = 0; nt < 4; ++nt)
                    mma_bf16(acc[mt][nt], af[mt], bh[nt]);

            // B lo fragments; hi * lo
#pragma unroll
            for (int nt = 0; nt < 4; ++nt) {
                if (BTRANS) {
                    uint32_t ad = smaddr(&sBl[(wn + nt * 8 + (lane & 7)) * AROW])
                                + ks * 32 + (((lane >> 3) & 1) << 4);
                    ldsm_x2(bl[nt], ad);
                } else {
                    uint32_t ad = smaddr(&sBl[(ks * 16 + (lane & 15)) * BROWN + wn + nt * 8]);
                    ldsm_x2t(bl[nt], ad);
                }
            }
#pragma unroll
            for (int mt = 0; mt < 4; ++mt)
#pragma unroll
                for (int nt = 0; nt < 4; ++nt)
                    mma_bf16(acc[mt][nt], af[mt], bl[nt]);

            // A lo fragments; lo * hi
#pragma unroll
            for (int mt = 0; mt < 4; ++mt)
                ldsm_x4(af[mt], smaddr(&sAl[(wm + mt * 16 + arow_off) * AROW]) + akb);
#pragma unroll
            for (int mt = 0; mt < 4; ++mt)
#pragma unroll
                for (int nt = 0; nt < 4; ++nt)
                    mma_bf16(acc[mt][nt], af[mt], bh[nt]);
        }
        __syncthreads();
    }

    // ---- epilogue ----
#pragma unroll
    for (int mt = 0; mt < 4; ++mt) {
#pragma unroll
        for (int nt = 0; nt < 4; ++nt) {
            int r = wm + mt * 16 + (lane >> 2);
            int c = wn + nt * 8 + ((lane & 3) << 1);
            float2 v0 = make_float2(alpha * acc[mt][nt][0], alpha * acc[mt][nt][1]);
            float2 v1 = make_float2(alpha * acc[mt][nt][2], alpha * acc[mt][nt][3]);
            *(float2*)&C[(size_t)r * ldc + c]       = v0;
            *(float2*)&C[(size_t)(r + 8) * ldc + c] = v1;
        }
    }
}

// ---------------------------------------------------------------------------
// Fused QKV projection: one launch, N = 2048(Q) + 1024(K) + 1024(V).
// Per-tile weight-pointer select; everything else identical to proj_mma.
// ---------------------------------------------------------------------------
__global__ __launch_bounds__(256, 2) void qkv_mma(
    const float* __restrict__ x,
    const float* __restrict__ wq, const float* __restrict__ wk,
    const float* __restrict__ wv,
    float* __restrict__ q, float* __restrict__ k, float* __restrict__ v)
{
    const int n0 = blockIdx.x * 128;
    const float* A = x + (size_t)blockIdx.y * 128 * DD;

    if (n0 < HH * HD) {
        const float* B = wq + (size_t)n0 * DD;
        float* C = q + (size_t)blockIdx.y * 128 * (HH * HD) + n0;
        gemm_core<true>(A, DD, B, DD, C, HH * HD, DD, 1.0f);
    } else if (n0 < HH * HD + KVH * HD) {
        const int m = n0 - HH * HD;
        const float* B = wk + (size_t)m * DD;
        float* C = k + (size_t)blockIdx.y * 128 * (KVH * HD) + m;
        gemm_core<true>(A, DD, B, DD, C, KVH * HD, DD, 1.0f);
    } else {
        const int m = n0 - HH * HD - KVH * HD;
        const float* B = wv + (size_t)m * DD;
        float* C = v + (size_t)blockIdx.y * 128 * (KVH * HD) + m;
        gemm_core<true>(A, DD, B, DD, C, KVH * HD, DD, 1.0f);
    }
}

// WO projection (round-2 proj_mma)
__global__ __launch_bounds__(256, 2) void proj_mma(
    int K, const float* __restrict__ A, int lda,
    const float* __restrict__ B, int ldb, float* __restrict__ C, int ldc)
{
    const float* Ab = A + (size_t)blockIdx.y * 128 * lda;
    const float* Bb = B + (size_t)blockIdx.x * 128 * ldb;
    float* Cb = C + (size_t)blockIdx.y * 128 * ldc + (size_t)blockIdx.x * 128;
    gemm_core<true>(Ab, lda, Bb, ldb, Cb, ldc, K, 1.0f);
}

// ---------------------------------------------------------------------------
// Scores; upper-triangle tiles write zeros (pure STG, overlaps compute tiles)
// ---------------------------------------------------------------------------
__global__ __launch_bounds__(256, 2) void score_mma(
    const float* __restrict__ q, const float* __restrict__ k,
    float* __restrict__ attn)
{
    const int bh = blockIdx.z;
    float* Cbase = attn + (size_t)bh * SS * SS
                 + (size_t)blockIdx.y * 128 * SS + (size_t)blockIdx.x * 128;
    if (blockIdx.x > blockIdx.y) {
        // zero the 128x128 tile (owns the [span, SS) region of its rows)
        const float4 z = make_float4(0.f, 0.f, 0.f, 0.f);
        for (int t = threadIdx.x; t < 128 * 32; t += 256) {
            int r = t >> 5, c = (t & 31) << 2;
            *(float4*)&Cbase[(size_t)r * SS + c] = z;
        }
        return;
    }
    const int h = bh % HH, b = bh / HH, kv = h / GG;
    const float* A = q + ((size_t)b * SS * HH + h) * HD
                       + (size_t)blockIdx.y * 128 * (HH * HD);
    const float* B = k + ((size_t)b * SS * KVH + kv) * HD
                       + (size_t)blockIdx.x * 128 * (KVH * HD);
    gemm_core<true>(A, HH * HD, B, KVH * HD, Cbase, SS, HD, SCALE);
}

// AV (round-2 av_mma, NN form, fp32 in/out)
__global__ __launch_bounds__(256, 2) void av_mma(
    const float* __restrict__ attn, const float* __restrict__ v,
    float* __restrict__ o)
{
    const int bh = blockIdx.z;
    const int h = bh % HH, b = bh / HH, kv = h / GG;
    const float* A = attn + (size_t)bh * SS * SS + (size_t)blockIdx.y * 128 * SS;
    const float* B = v + ((size_t)b * SS * KVH + kv) * HD;
    float* C = o + ((size_t)b * SS * HH + h) * HD
                 + (size_t)blockIdx.y * 128 * (HH * HD);
    const int K = (int)blockIdx.y * 128 + 128;   // causal: t <= q_max in tile
    gemm_core<false>(A, SS, B, KVH * HD, C, HH * HD, K, 1.0f);
}

// ---------------------------------------------------------------------------
// Fused RMSNorm + RoPE, in place (fp32), round-2 version.
// ---------------------------------------------------------------------------
__global__ __launch_bounds__(128) void normrope_kernel(
    float* __restrict__ data, const float* __restrict__ w,
    const float* __restrict__ cosb, const float* __restrict__ sinb,
    int nheads)
{
    const int idx = blockIdx.x;
    const int h = idx % nheads;
    const int s = (idx / nheads) % SS;
    const int b = idx / (nheads * SS);
    const int t = threadIdx.x;

    float* ptr = data + (((size_t)b * SS + s) * nheads + h) * HD;
    float v = ptr[t];

    float ss = v * v;
#pragma unroll
    for (int o = 16; o; o >>= 1) ss += __shfl_xor_sync(0xffffffffu, ss, o);

    __shared__ float ws[4];
    __shared__ float sh[128];
    const int lane = t & 31, wid = t >> 5;
    if (lane == 0) ws[wid] = ss;
    __syncthreads();
    float var = (ws[0] + ws[1] + ws[2] + ws[3]) * (1.0f / HD);
    float xn = v * rsqrtf(var + 1e-6f) * w[t];
    sh[t] = xn;
    __syncthreads();
    float rot = (t < 64) ? -sh[t + 64] : sh[t - 64];

    const float* cp = cosb + ((size_t)b * SS + s) * HD;
    const float* sp = sinb + ((size_t)b * SS + s) * HD;
    ptr[t] = xn * cp[t] + rot * sp[t];
}

// ---------------------------------------------------------------------------
// Row softmax (causal). Writes ONLY [0, span) — zeros beyond come from the
// score kernel's zero tiles. Warp-shuffle reductions (3 syncs total).
// ---------------------------------------------------------------------------
__global__ __launch_bounds__(256) void softmax_kernel(float* __restrict__ attn)
{
    __shared__ float buf[SS];
    __shared__ float redm[8];
    __shared__ float reds[8];
    const int row = blockIdx.x;
    const int qi = row & (SS - 1);
    const int valid = qi + 1;
    const int span = ((qi >> 7) + 1) << 7;     // next multiple of 128
    float* base = attn + (size_t)row * SS;
    const int tid = threadIdx.x;
    const int lane = tid & 31, wrp = tid >> 5;

    float m = -1e30f;
    for (int t = tid * 4; t < span; t += 1024) {
        float4 v = *(const float4*)(base + t);
        v.x = (t + 0 < valid) ? v.x : -1e30f;
        v.y = (t + 1 < valid) ? v.y : -1e30f;
        v.z = (t + 2 < valid) ? v.z : -1e30f;
        v.w = (t + 3 < valid) ? v.w : -1e30f;
        *(float4*)(buf + t) = v;
        m = fmaxf(m, fmaxf(fmaxf(v.x, v.y), fmaxf(v.z, v.w)));
    }
#pragma unroll
    for (int o = 16; o; o >>= 1) m = fmaxf(m, __shfl_xor_sync(0xffffffffu, m, o));
    if (lane == 0) redm[wrp] = m;
    __syncthreads();
    float mx = redm[0];
#pragma unroll
    for (int i = 1; i < 8; ++i) mx = fmaxf(mx, redm[i]);

    float sum = 0.f;
    for (int t = tid * 4; t < span; t += 1024) {
        float4 v = *(const float4*)(buf + t);
        v.x = expf(v.x - mx); v.y = expf(v.y - mx);
        v.z = expf(v.z - mx); v.w = expf(v.w - mx);
        *(float4*)(buf + t) = v;
        sum += v.x + v.y + v.z + v.w;
    }
#pragma unroll
    for (int o = 16; o; o >>= 1) sum += __shfl_xor_sync(0xffffffffu, sum, o);
    if (lane == 0) reds[wrp] = sum;
    __syncthreads();
    float tot = reds[0] + reds[1] + reds[2] + reds[3]
              + reds[4] + reds[5] + reds[6] + reds[7];
    const float inv = 1.0f / tot;

    for (int t = tid * 4; t < span; t += 1024) {
        float4 v = *(const float4*)(buf + t);
        v.x *= inv; v.y *= inv; v.z *= inv; v.w *= inv;
        *(float4*)(base + t) = v;
    }
}

// ---------------- launch ----------------
extern "C" void kernel_launch(void* const* d_in, const int* in_sizes, int n_in,
                              void* d_out, int out_size)
{
    const float* x    = (const float*)d_in[0];
    const float* cosb = (const float*)d_in[1];
    const float* sinb = (const float*)d_in[2];
    // d_in[3] = attention_mask (pure causal; applied analytically)
    const float* wq   = (const float*)d_in[4];
    const float* wk   = (const float*)d_in[5];
    const float* wv   = (const float*)d_in[6];
    const float* wo   = (const float*)d_in[7];
    const float* qw   = (const float*)d_in[8];
    const float* kw   = (const float*)d_in[9];

    float* out  = (float*)d_out;                    // (B,S,H*HD)
    float* attn = out + (size_t)BB * SS * HH * HD;  // (B,H,S,S)

    float *pq, *pk, *pv, *po;
    cudaGetSymbolAddress((void**)&pq, g_q);
    cudaGetSymbolAddress((void**)&pk, g_k);
    cudaGetSymbolAddress((void**)&pv, g_v);
    cudaGetSymbolAddress((void**)&po, g_o);

    const int BS = BB * SS;   // 4096
    dim3 blk(256);

    // Fused QKV projection: grid = (N_total/128, M/128) = (32, 32)
    qkv_mma<<<dim3(32, BS / 128), blk>>>(x, wq, wk, wv, pq, pk, pv);

    // RMSNorm + RoPE (in place, fp32)
    normrope_kernel<<<BB * SS * HH, 128>>>(pq, qw, cosb, sinb, HH);
    normrope_kernel<<<BB * SS * KVH, 128>>>(pk, kw, cosb, sinb, KVH);

    // Scores (causal; upper tiles zero-filled), softmax (span-only), AV
    score_mma<<<dim3(SS / 128, SS / 128, BB * HH), blk>>>(pq, pk, attn);
    softmax_kernel<<<BB * HH * SS, 256>>>(attn);
    av_mma<<<dim3(1, SS / 128, BB * HH), blk>>>(attn, pv, po);

    // Output projection: out = O @ Wo^T
    proj_mma<<<dim3(DD / 128, BS / 128), blk>>>(
        HH * HD, po, HH * HD, wo, HH * HD, out, DD);
}